// round 1
// baseline (speedup 1.0000x reference)
#include <cuda_runtime.h>
#include <cuda_bf16.h>
#include <cstdint>

#define EPS_ 1e-3f
#define B_   2
#define H_   96
#define W_   96
#define C_   64
#define CQ   8
#define HW_  9216
#define BHW  (B_*HW_)

// ---------------- scratch (static device arrays; no allocation) ----------------
__device__ float          g_q[BHW * CQ];     // Q rows, fp32
__device__ float          g_k[BHW * CQ];     // K rows, fp32
__device__ float          g_v[BHW * C_];     // V rows, fp32
__device__ __nv_bfloat16  g_vs[BHW * C_];    // V * gamma / rowsum, bf16
__device__ float          g_rmax[BHW];
__device__ float          g_rsum[BHW];

// ---------------- kernel 1: fused convs + BN + ReLU ----------------
// one block per pixel, 64 threads
__global__ void prep_kernel(const float* __restrict__ x,
    const float* __restrict__ Wq, const float* __restrict__ bq,
    const float* __restrict__ gq, const float* __restrict__ betaq,
    const float* __restrict__ mq, const float* __restrict__ vq,
    const float* __restrict__ Wk, const float* __restrict__ bk,
    const float* __restrict__ gk, const float* __restrict__ betak,
    const float* __restrict__ mk, const float* __restrict__ vk,
    const float* __restrict__ Wv, const float* __restrict__ bv)
{
    __shared__ float xs[5][C_];   // 0=center 1=left 2=right 3=up 4=down
    int pix = blockIdx.x;
    int b = pix / HW_;
    int n = pix - b * HW_;
    int h = n / W_, w = n - h * W_;
    int c = threadIdx.x;
    const float* xb = x + (size_t)b * HW_ * C_;

    xs[0][c] = xb[(h * W_ + w) * C_ + c];
    xs[1][c] = (w > 0)      ? xb[(h * W_ + w - 1) * C_ + c] : 0.f;
    xs[2][c] = (w < W_ - 1) ? xb[(h * W_ + w + 1) * C_ + c] : 0.f;
    xs[3][c] = (h > 0)      ? xb[((h - 1) * W_ + w) * C_ + c] : 0.f;
    xs[4][c] = (h < H_ - 1) ? xb[((h + 1) * W_ + w) * C_ + c] : 0.f;
    __syncthreads();

    // V = 1x1 conv + bias
    float acc = bv[c];
    #pragma unroll 8
    for (int ci = 0; ci < C_; ci++)
        acc = fmaf(xs[0][ci], Wv[ci * C_ + c], acc);
    g_v[(size_t)pix * C_ + c] = acc;

    if (c < CQ) {
        // Q = (1,3) conv over width: taps (w-1, w, w+1)
        float s = 0.f;
        #pragma unroll 8
        for (int ci = 0; ci < C_; ci++) {
            s = fmaf(xs[1][ci], Wq[(0 * C_ + ci) * CQ + c], s);
            s = fmaf(xs[0][ci], Wq[(1 * C_ + ci) * CQ + c], s);
            s = fmaf(xs[2][ci], Wq[(2 * C_ + ci) * CQ + c], s);
        }
        float sc  = gq[c] * rsqrtf(vq[c] + EPS_);
        float val = fmaf(s + bq[c] - mq[c], sc, betaq[c]);
        g_q[pix * CQ + c] = fmaxf(val, 0.f);
    } else if (c < 2 * CQ) {
        // K = (3,1) conv over height: taps (h-1, h, h+1)
        int cc = c - CQ;
        float s = 0.f;
        #pragma unroll 8
        for (int ci = 0; ci < C_; ci++) {
            s = fmaf(xs[3][ci], Wk[(0 * C_ + ci) * CQ + cc], s);
            s = fmaf(xs[0][ci], Wk[(1 * C_ + ci) * CQ + cc], s);
            s = fmaf(xs[4][ci], Wk[(2 * C_ + ci) * CQ + cc], s);
        }
        float sc  = gk[cc] * rsqrtf(vk[cc] + EPS_);
        float val = fmaf(s + bk[cc] - mk[cc], sc, betak[cc]);
        g_k[pix * CQ + cc] = fmaxf(val, 0.f);
    }
}

// ---------------- kernel 2: per-row online softmax stats (max, sum) ----------------
// grid (HW/128, B), 256 threads; thread owns row n = tid&127, half of m (parity tid>>7)
__global__ void pass1_kernel()
{
    __shared__ float pm[128], ps[128];
    int b  = blockIdx.y;
    int nl = threadIdx.x & 127;
    int p  = threadIdx.x >> 7;
    int n  = blockIdx.x * 128 + nl;

    const float4* qr = (const float4*)&g_q[(b * HW_ + n) * CQ];
    float4 q0 = qr[0], q1 = qr[1];

    const float4* kb = (const float4*)&g_k[(size_t)b * HW_ * CQ];

    float rmax = -INFINITY, rsum = 0.f;
    #pragma unroll 4
    for (int j = 0; j < HW_ / 2; j++) {
        int m = 2 * j + p;               // uniform across warp
        float4 k0 = kb[m * 2];
        float4 k1 = kb[m * 2 + 1];
        float s = q0.x * k0.x;
        s = fmaf(q0.y, k0.y, s);
        s = fmaf(q0.z, k0.z, s);
        s = fmaf(q0.w, k0.w, s);
        s = fmaf(q1.x, k1.x, s);
        s = fmaf(q1.y, k1.y, s);
        s = fmaf(q1.z, k1.z, s);
        s = fmaf(q1.w, k1.w, s);
        if (s > rmax) {
            rsum = rsum * __expf(rmax - s) + 1.0f;
            rmax = s;
        } else {
            rsum += __expf(s - rmax);
        }
    }
    __syncthreads();
    if (p == 1) { pm[nl] = rmax; ps[nl] = rsum; }
    __syncthreads();
    if (p == 0) {
        float m2 = pm[nl], s2 = ps[nl];
        float M = fmaxf(rmax, m2);
        float S = rsum * __expf(rmax - M) + s2 * __expf(m2 - M);
        g_rmax[b * HW_ + n] = M;
        g_rsum[b * HW_ + n] = S;
    }
}

// ---------------- kernel 3: vs = bf16(gamma * v / rowsum) ----------------
__global__ void scalev_kernel(const float* __restrict__ gamma)
{
    int idx = blockIdx.x * 256 + threadIdx.x;   // over BHW*C
    float inv = gamma[0] / g_rsum[idx >> 6];
    g_vs[idx] = __float2bfloat16(g_v[idx] * inv);
}

// ---------------- kernel 4: fused P-recompute + bf16 MMA + residual epilogue ----------------
// D[c][m] = sum_n vs[n][c] * exp(q_n . k_m - rowmax[n]);  out[b][m][c] = D + x[b][m][c]
// grid (HW/64, B), 256 threads (8 warps, 2x4 warp tiling over 64c x 64m)

__device__ __forceinline__ void mma_bf16(float* d, const unsigned* a, const unsigned* bb)
{
    asm volatile(
        "mma.sync.aligned.m16n8k16.row.col.f32.bf16.bf16.f32 "
        "{%0,%1,%2,%3}, {%4,%5,%6,%7}, {%8,%9}, {%0,%1,%2,%3};\n"
        : "+f"(d[0]), "+f"(d[1]), "+f"(d[2]), "+f"(d[3])
        : "r"(a[0]), "r"(a[1]), "r"(a[2]), "r"(a[3]), "r"(bb[0]), "r"(bb[1]));
}

#define NT 64   // m per block
#define KC 64   // n per chunk

__global__ __launch_bounds__(256, 2)
void pass2_kernel(const float* __restrict__ x, float* __restrict__ out)
{
    __shared__ float          kt[NT][8];        // K rows for this m-tile
    __shared__ float          qc[KC][12];       // Q rows for n-chunk (padded, 16B-aligned rows)
    __shared__ float          mxs[KC];
    __shared__ __nv_bfloat16  vsT[C_][72];      // [c][n] (padded rows for bank spread)
    __shared__ __nv_bfloat16  Pt[NT][72];       // [m][n]

    int b    = blockIdx.y;
    int m0   = blockIdx.x * NT;
    int t    = threadIdx.x;
    int lane = t & 31;
    int warp = t >> 5;
    int g    = lane >> 2;
    int tq   = lane & 3;
    int wc   = warp >> 2;          // 0..1 : c-half
    int wm   = warp & 3;           // 0..3 : m-quarter
    int pn   = t & 63;             // producer: row n
    int pmb  = (t >> 6) * 16;      // producer: m base (uniform per warp)

    // K tile for the m columns of this block (loaded once)
    for (int i = t; i < NT * 8; i += 256)
        ((float*)kt)[i] = g_k[((size_t)b * HW_ + m0) * 8 + i];

    float acc[2][2][4];
    #pragma unroll
    for (int i = 0; i < 2; i++)
        #pragma unroll
        for (int j = 0; j < 2; j++)
            #pragma unroll
            for (int r = 0; r < 4; r++) acc[i][j][r] = 0.f;

    for (int ck = 0; ck < HW_ / KC; ck++) {
        int n0 = ck * KC;
        // ---- cooperative loads for this n-chunk ----
        for (int i = t; i < KC * 8; i += 256)
            qc[i >> 3][i & 7] = g_q[((size_t)b * HW_ + n0) * 8 + i];
        if (t < KC) mxs[t] = g_rmax[b * HW_ + n0 + t];
        for (int i = t; i < KC * C_; i += 256) {
            int nn = i >> 6, cc = i & 63;
            vsT[cc][nn] = g_vs[((size_t)(b * HW_ + n0 + nn)) * C_ + cc];
        }
        __syncthreads();

        // ---- produce P^T tile: Pt[m][n] = exp(q_n . k_m - max_n), bf16 ----
        {
            float4 qv0 = *(const float4*)&qc[pn][0];
            float4 qv1 = *(const float4*)&qc[pn][4];
            float  mx  = mxs[pn];
            #pragma unroll 4
            for (int i = 0; i < 16; i++) {
                int m = pmb + i;                       // uniform per warp
                float4 k0 = *(const float4*)&kt[m][0];
                float4 k1 = *(const float4*)&kt[m][4];
                float s = qv0.x * k0.x;
                s = fmaf(qv0.y, k0.y, s);
                s = fmaf(qv0.z, k0.z, s);
                s = fmaf(qv0.w, k0.w, s);
                s = fmaf(qv1.x, k1.x, s);
                s = fmaf(qv1.y, k1.y, s);
                s = fmaf(qv1.z, k1.z, s);
                s = fmaf(qv1.w, k1.w, s);
                Pt[m][pn] = __float2bfloat16(__expf(s - mx));
            }
        }
        __syncthreads();

        // ---- consume: D(64x64) += VsT(64xKC) @ P(KCx64) via m16n8k16 bf16 ----
        #pragma unroll
        for (int ks = 0; ks < KC / 16; ks++) {
            int nb = ks * 16;
            unsigned a[2][4], bfr[2][2];
            #pragma unroll
            for (int tc = 0; tc < 2; tc++) {
                int cb = wc * 32 + tc * 16;
                a[tc][0] = *(const unsigned*)&vsT[cb + g    ][nb + 2 * tq    ];
                a[tc][1] = *(const unsigned*)&vsT[cb + g + 8][nb + 2 * tq    ];
                a[tc][2] = *(const unsigned*)&vsT[cb + g    ][nb + 2 * tq + 8];
                a[tc][3] = *(const unsigned*)&vsT[cb + g + 8][nb + 2 * tq + 8];
            }
            #pragma unroll
            for (int tn = 0; tn < 2; tn++) {
                int mb2 = wm * 16 + tn * 8;
                bfr[tn][0] = *(const unsigned*)&Pt[mb2 + g][nb + 2 * tq    ];
                bfr[tn][1] = *(const unsigned*)&Pt[mb2 + g][nb + 2 * tq + 8];
            }
            #pragma unroll
            for (int tc = 0; tc < 2; tc++)
                #pragma unroll
                for (int tn = 0; tn < 2; tn++)
                    mma_bf16(acc[tc][tn], a[tc], bfr[tn]);
        }
        __syncthreads();
    }

    // ---- epilogue: out[b][m][c] = D[c][m] + x[b][m][c]  (gamma folded into vs) ----
    #pragma unroll
    for (int tc = 0; tc < 2; tc++) {
        #pragma unroll
        for (int tn = 0; tn < 2; tn++) {
            int c0 = wc * 32 + tc * 16 + g;
            int m1 = m0 + wm * 16 + tn * 8 + 2 * tq;
            size_t i00 = ((size_t)(b * HW_ + m1)) * C_ + c0;   // (m1,   c0)
            size_t i10 = i00 + C_;                             // (m1+1, c0)
            out[i00]     = acc[tc][tn][0] + x[i00];
            out[i10]     = acc[tc][tn][1] + x[i10];
            out[i00 + 8] = acc[tc][tn][2] + x[i00 + 8];
            out[i10 + 8] = acc[tc][tn][3] + x[i10 + 8];
        }
    }
}

// ---------------- launch ----------------
extern "C" void kernel_launch(void* const* d_in, const int* in_sizes, int n_in,
                              void* d_out, int out_size)
{
    const float* x     = (const float*)d_in[0];
    const float* Wq    = (const float*)d_in[1];
    const float* bq    = (const float*)d_in[2];
    const float* gq    = (const float*)d_in[3];
    const float* betaq = (const float*)d_in[4];
    const float* mq    = (const float*)d_in[5];
    const float* vq    = (const float*)d_in[6];
    const float* Wk    = (const float*)d_in[7];
    const float* bk    = (const float*)d_in[8];
    const float* gk    = (const float*)d_in[9];
    const float* betak = (const float*)d_in[10];
    const float* mk    = (const float*)d_in[11];
    const float* vk    = (const float*)d_in[12];
    const float* Wv    = (const float*)d_in[13];
    const float* bv    = (const float*)d_in[14];
    const float* gamma = (const float*)d_in[15];
    float* out = (float*)d_out;

    prep_kernel<<<BHW, C_>>>(x, Wq, bq, gq, betaq, mq, vq,
                             Wk, bk, gk, betak, mk, vk, Wv, bv);
    pass1_kernel<<<dim3(HW_ / 128, B_), 256>>>();
    scalev_kernel<<<(BHW * C_) / 256, 256>>>(gamma);
    pass2_kernel<<<dim3(HW_ / NT, B_), 256>>>(x, out);
}

// round 2
// speedup vs baseline: 4.3125x; 4.3125x over previous
#include <cuda_runtime.h>
#include <cuda_bf16.h>
#include <cstdint>

#define EPS_ 1e-3f
#define B_   2
#define H_   96
#define W_   96
#define C_   64
#define CQ   8
#define HW_  9216
#define BHW  (B_*HW_)
#define NMT  72            // number of 128-wide m tiles

// ---------------- scratch (static device arrays; no allocation) ----------------
__device__ float          g_q[BHW * CQ];               // Q rows, fp32 [n][8]
__device__ float          g_k[BHW * CQ];               // K rows, fp32 [m][8]
__device__ float          g_v[BHW * C_];               // V rows, fp32 [n][c]
__device__ __nv_bfloat16  g_vsT[(size_t)B_ * C_ * HW_]; // Vs^T [b][c][n], bf16
__device__ float          g_part[(size_t)B_ * NMT * HW_]; // partial colsums [b][mt][n]
__device__ float          g_rsum[BHW];                 // softmax denominators
__device__ __nv_bfloat16  g_pt[(size_t)BHW * HW_];     // P^T [b][m][n] = exp(q_n.k_m), bf16

// ---------------- helpers ----------------
__device__ __forceinline__ unsigned f2tf32(float f) {
    unsigned r;
    asm("cvt.rna.tf32.f32 %0, %1;" : "=r"(r) : "f"(f));
    return r;
}
__device__ __forceinline__ unsigned packbf2(float hi, float lo) {
    unsigned r;
    asm("cvt.rn.bf16x2.f32 %0, %1, %2;" : "=r"(r) : "f"(hi), "f"(lo));
    return r;
}
__device__ __forceinline__ void mma_tf32(float* d, const unsigned* a, unsigned b0, unsigned b1) {
    asm volatile(
        "mma.sync.aligned.m16n8k8.row.col.f32.tf32.tf32.f32 "
        "{%0,%1,%2,%3}, {%4,%5,%6,%7}, {%8,%9}, {%0,%1,%2,%3};\n"
        : "+f"(d[0]), "+f"(d[1]), "+f"(d[2]), "+f"(d[3])
        : "r"(a[0]), "r"(a[1]), "r"(a[2]), "r"(a[3]), "r"(b0), "r"(b1));
}
__device__ __forceinline__ void mma_bf16(float* d, const unsigned* a, unsigned b0, unsigned b1) {
    asm volatile(
        "mma.sync.aligned.m16n8k16.row.col.f32.bf16.bf16.f32 "
        "{%0,%1,%2,%3}, {%4,%5,%6,%7}, {%8,%9}, {%0,%1,%2,%3};\n"
        : "+f"(d[0]), "+f"(d[1]), "+f"(d[2]), "+f"(d[3])
        : "r"(a[0]), "r"(a[1]), "r"(a[2]), "r"(a[3]), "r"(b0), "r"(b1));
}
__device__ __forceinline__ void ldsm4(unsigned* r, const void* p) {
    unsigned a = (unsigned)__cvta_generic_to_shared(p);
    asm volatile("ldmatrix.sync.aligned.m8n8.x4.shared.b16 {%0,%1,%2,%3}, [%4];"
                 : "=r"(r[0]), "=r"(r[1]), "=r"(r[2]), "=r"(r[3]) : "r"(a));
}
__device__ __forceinline__ void cpa16(void* dst, const void* src) {
    unsigned d = (unsigned)__cvta_generic_to_shared(dst);
    asm volatile("cp.async.cg.shared.global [%0], [%1], 16;" :: "r"(d), "l"(src));
}
__device__ __forceinline__ void cpa_commit() { asm volatile("cp.async.commit_group;"); }
template <int N>
__device__ __forceinline__ void cpa_wait() { asm volatile("cp.async.wait_group %0;" :: "n"(N)); }

// ---------------- kernel 1: fused convs + BN + ReLU ----------------
__global__ void prep_kernel(const float* __restrict__ x,
    const float* __restrict__ Wq, const float* __restrict__ bq,
    const float* __restrict__ gq, const float* __restrict__ betaq,
    const float* __restrict__ mq, const float* __restrict__ vq,
    const float* __restrict__ Wk, const float* __restrict__ bk,
    const float* __restrict__ gk, const float* __restrict__ betak,
    const float* __restrict__ mk, const float* __restrict__ vk,
    const float* __restrict__ Wv, const float* __restrict__ bv)
{
    __shared__ float xs[5][C_];   // 0=center 1=left 2=right 3=up 4=down
    int pix = blockIdx.x;
    int b = pix / HW_;
    int n = pix - b * HW_;
    int h = n / W_, w = n - h * W_;
    int c = threadIdx.x;
    const float* xb = x + (size_t)b * HW_ * C_;

    xs[0][c] = xb[(h * W_ + w) * C_ + c];
    xs[1][c] = (w > 0)      ? xb[(h * W_ + w - 1) * C_ + c] : 0.f;
    xs[2][c] = (w < W_ - 1) ? xb[(h * W_ + w + 1) * C_ + c] : 0.f;
    xs[3][c] = (h > 0)      ? xb[((h - 1) * W_ + w) * C_ + c] : 0.f;
    xs[4][c] = (h < H_ - 1) ? xb[((h + 1) * W_ + w) * C_ + c] : 0.f;
    __syncthreads();

    float acc = bv[c];
    #pragma unroll 8
    for (int ci = 0; ci < C_; ci++)
        acc = fmaf(xs[0][ci], Wv[ci * C_ + c], acc);
    g_v[(size_t)pix * C_ + c] = acc;

    if (c < CQ) {
        float s = 0.f;
        #pragma unroll 8
        for (int ci = 0; ci < C_; ci++) {
            s = fmaf(xs[1][ci], Wq[(0 * C_ + ci) * CQ + c], s);
            s = fmaf(xs[0][ci], Wq[(1 * C_ + ci) * CQ + c], s);
            s = fmaf(xs[2][ci], Wq[(2 * C_ + ci) * CQ + c], s);
        }
        float sc  = gq[c] * rsqrtf(vq[c] + EPS_);
        float val = fmaf(s + bq[c] - mq[c], sc, betaq[c]);
        g_q[pix * CQ + c] = fmaxf(val, 0.f);
    } else if (c < 2 * CQ) {
        int cc = c - CQ;
        float s = 0.f;
        #pragma unroll 8
        for (int ci = 0; ci < C_; ci++) {
            s = fmaf(xs[3][ci], Wk[(0 * C_ + ci) * CQ + cc], s);
            s = fmaf(xs[0][ci], Wk[(1 * C_ + ci) * CQ + cc], s);
            s = fmaf(xs[4][ci], Wk[(2 * C_ + ci) * CQ + cc], s);
        }
        float sc  = gk[cc] * rsqrtf(vk[cc] + EPS_);
        float val = fmaf(s + bk[cc] - mk[cc], sc, betak[cc]);
        g_k[pix * CQ + cc] = fmaxf(val, 0.f);
    }
}

// ---------------- kernel 2: P^T tile = exp(S^T) via tf32 MMA + store + colsum partials ----------------
// block = one 128m x 128n tile. S^T[m][n] = sum_k K[m][k]*Q[n][k].
// warp w owns n columns [16w,16w+16); loops over 8 m-subtiles of 16.
__global__ __launch_bounds__(256)
void exp_kernel()
{
    __shared__ float                       ks[128][12];   // K tile, padded
    __shared__ __align__(16) __nv_bfloat16 Ps[128][136];  // P^T tile, padded rows (272B)

    int b  = blockIdx.z;
    int mt = blockIdx.y;
    int nt = blockIdx.x;
    int m0 = mt * 128, n0 = nt * 128;
    int t = threadIdx.x, lane = t & 31, w = t >> 5;
    int g = lane >> 2, tq = lane & 3;
    size_t bHW = (size_t)b * HW_;

    // stage K tile (reduction operand A rows)
    for (int i = t; i < 1024; i += 256)
        ks[i >> 3][i & 7] = g_k[(bHW + m0 + (i >> 3)) * 8 + (i & 7)];

    // per-warp fixed B fragments from Q (cols of S^T): rows n0+16w+g and +8
    unsigned bq[4];
    {
        const float* qp  = &g_q[(bHW + n0 + 16 * w + g) * 8];
        bq[0] = f2tf32(qp[tq]);
        bq[1] = f2tf32(qp[tq + 4]);
        bq[2] = f2tf32(qp[64 + tq]);       // +8 rows
        bq[3] = f2tf32(qp[64 + tq + 4]);
    }
    __syncthreads();

    float cs0 = 0.f, cs1 = 0.f, cs2 = 0.f, cs3 = 0.f;   // colsum accum (cols fixed per thread)

    #pragma unroll
    for (int i = 0; i < 8; i++) {
        unsigned a[4];
        a[0] = f2tf32(ks[16 * i + g    ][tq    ]);
        a[1] = f2tf32(ks[16 * i + g + 8][tq    ]);
        a[2] = f2tf32(ks[16 * i + g    ][tq + 4]);
        a[3] = f2tf32(ks[16 * i + g + 8][tq + 4]);

        float d[4] = {0.f, 0.f, 0.f, 0.f};
        float e[4] = {0.f, 0.f, 0.f, 0.f};
        mma_tf32(d, a, bq[0], bq[1]);   // n-octet 16w
        mma_tf32(e, a, bq[2], bq[3]);   // n-octet 16w+8

        float p0 = __expf(d[0]), p1 = __expf(d[1]), p2 = __expf(d[2]), p3 = __expf(d[3]);
        float q0 = __expf(e[0]), q1 = __expf(e[1]), q2 = __expf(e[2]), q3 = __expf(e[3]);

        cs0 += p0 + p2;  cs1 += p1 + p3;
        cs2 += q0 + q2;  cs3 += q1 + q3;

        int c0 = 16 * w + 2 * tq;
        *(unsigned*)&Ps[16 * i + g    ][c0    ] = packbf2(p1, p0);
        *(unsigned*)&Ps[16 * i + g + 8][c0    ] = packbf2(p3, p2);
        *(unsigned*)&Ps[16 * i + g    ][c0 + 8] = packbf2(q1, q0);
        *(unsigned*)&Ps[16 * i + g + 8][c0 + 8] = packbf2(q3, q2);
    }
    __syncthreads();

    // coalesced 16B store of the tile to global P^T
    for (int i = t; i < 2048; i += 256) {
        int row = i >> 4, seg = i & 15;
        uint4 v = *(const uint4*)&Ps[row][seg * 8];
        *(uint4*)&g_pt[(bHW + m0 + row) * HW_ + n0 + seg * 8] = v;
    }

    // reduce colsums over the 8 g-lanes sharing each column
    #pragma unroll
    for (int s = 16; s >= 4; s >>= 1) {
        cs0 += __shfl_xor_sync(0xffffffffu, cs0, s);
        cs1 += __shfl_xor_sync(0xffffffffu, cs1, s);
        cs2 += __shfl_xor_sync(0xffffffffu, cs2, s);
        cs3 += __shfl_xor_sync(0xffffffffu, cs3, s);
    }
    if (lane < 4) {
        float* pp = &g_part[((size_t)b * NMT + mt) * HW_ + n0 + 16 * w];
        pp[2 * tq]     = cs0;
        pp[2 * tq + 1] = cs1;
        pp[2 * tq + 8] = cs2;
        pp[2 * tq + 9] = cs3;
    }
}

// ---------------- kernel 2b: reduce partial colsums -> rowsum ----------------
__global__ void rsum_kernel()
{
    int i = blockIdx.x * 256 + threadIdx.x;   // over BHW
    int b = i / HW_, n = i - b * HW_;
    float s = 0.f;
    #pragma unroll 8
    for (int mt = 0; mt < NMT; mt++)
        s += g_part[((size_t)b * NMT + mt) * HW_ + n];
    g_rsum[i] = s;
}

// ---------------- kernel 3: Vs^T = bf16(gamma * v / rowsum), transposed [b][c][n] ----------------
__global__ void scalev_kernel(const float* __restrict__ gamma)
{
    size_t o = (size_t)blockIdx.x * 256 + threadIdx.x;  // over B*C*HW, n fastest
    int n = (int)(o % HW_);
    int c = (int)((o / HW_) % C_);
    int b = (int)(o / ((size_t)HW_ * C_));
    float val = g_v[((size_t)(b * HW_ + n)) * C_ + c] * gamma[0] / g_rsum[b * HW_ + n];
    g_vsT[o] = __float2bfloat16(val);
}

// ---------------- kernel 4: D[c][m] = Vs^T @ P  (bf16 MMA, cp.async dbuf) + residual ----------------
// block = 64 m cols, all 64 c; reduction over n in chunks of 64.
__global__ __launch_bounds__(256)
void gemm_kernel(const float* __restrict__ x, float* __restrict__ out)
{
    __shared__ __align__(16) __nv_bfloat16 As[2][64][72];  // Vs^T chunk [c][n]
    __shared__ __align__(16) __nv_bfloat16 Bs[2][64][72];  // P^T chunk [m][n]

    int b  = blockIdx.y;
    int m0 = blockIdx.x * 64;
    int t = threadIdx.x, lane = t & 31, w = t >> 5;
    int g = lane >> 2, tq = lane & 3;
    int wc = w & 3;          // c quarter (16 rows)
    int wm = w >> 2;         // m half (32 cols)
    size_t bHW = (size_t)b * HW_;

    const __nv_bfloat16* Ag = &g_vsT[(size_t)b * C_ * HW_];
    const __nv_bfloat16* Bg = &g_pt[(bHW + m0) * HW_];

    float acc[4][4];
    #pragma unroll
    for (int i = 0; i < 4; i++)
        #pragma unroll
        for (int j = 0; j < 4; j++) acc[i][j] = 0.f;

    int lr = t >> 3, lseg = t & 7;             // 256 threads -> 32 rows x 8 segs per pass
    // prologue: chunk 0
    {
        int n0 = 0;
        #pragma unroll
        for (int k = 0; k < 2; k++) {
            int row = lr + k * 32;
            cpa16(&As[0][row][lseg * 8], Ag + (size_t)row * HW_ + n0 + lseg * 8);
            cpa16(&Bs[0][row][lseg * 8], Bg + (size_t)row * HW_ + n0 + lseg * 8);
        }
        cpa_commit();
    }

    const int NC = HW_ / 64;
    for (int ck = 0; ck < NC; ck++) {
        int buf = ck & 1;
        if (ck + 1 < NC) {
            int n0 = (ck + 1) * 64;
            #pragma unroll
            for (int k = 0; k < 2; k++) {
                int row = lr + k * 32;
                cpa16(&As[buf ^ 1][row][lseg * 8], Ag + (size_t)row * HW_ + n0 + lseg * 8);
                cpa16(&Bs[buf ^ 1][row][lseg * 8], Bg + (size_t)row * HW_ + n0 + lseg * 8);
            }
            cpa_commit();
            cpa_wait<1>();
        } else {
            cpa_wait<0>();
        }
        __syncthreads();

        #pragma unroll
        for (int ksx = 0; ksx < 4; ksx++) {
            int k0 = ksx * 16;
            unsigned a[4];
            ldsm4(a, &As[buf][16 * wc + (lane & 7) + ((lane >> 3) & 1) * 8][(lane >> 4) * 8 + k0]);
            #pragma unroll
            for (int p = 0; p < 2; p++) {
                unsigned bb[4];
                ldsm4(bb, &Bs[buf][32 * wm + 16 * p + (lane & 7) + ((lane >> 4) & 1) * 8]
                                  [k0 + ((lane >> 3) & 1) * 8]);
                mma_bf16(acc[2 * p    ], a, bb[0], bb[1]);
                mma_bf16(acc[2 * p + 1], a, bb[2], bb[3]);
            }
        }
        __syncthreads();
    }

    // epilogue: out[b][m][c] = D[c][m] + x[b][m][c]
    int c0 = 16 * wc + g;
    #pragma unroll
    for (int jo = 0; jo < 4; jo++) {
        int m = m0 + 32 * wm + 8 * jo + 2 * tq;
        size_t i00 = (bHW + m) * (size_t)C_ + c0;
        out[i00]          = acc[jo][0] + x[i00];
        out[i00 + C_]     = acc[jo][1] + x[i00 + C_];
        out[i00 + 8]      = acc[jo][2] + x[i00 + 8];
        out[i00 + C_ + 8] = acc[jo][3] + x[i00 + C_ + 8];
    }
}

// ---------------- launch ----------------
extern "C" void kernel_launch(void* const* d_in, const int* in_sizes, int n_in,
                              void* d_out, int out_size)
{
    const float* x     = (const float*)d_in[0];
    const float* Wq    = (const float*)d_in[1];
    const float* bq    = (const float*)d_in[2];
    const float* gq    = (const float*)d_in[3];
    const float* betaq = (const float*)d_in[4];
    const float* mq    = (const float*)d_in[5];
    const float* vq    = (const float*)d_in[6];
    const float* Wk    = (const float*)d_in[7];
    const float* bk    = (const float*)d_in[8];
    const float* gk    = (const float*)d_in[9];
    const float* betak = (const float*)d_in[10];
    const float* mk    = (const float*)d_in[11];
    const float* vk    = (const float*)d_in[12];
    const float* Wv    = (const float*)d_in[13];
    const float* bv    = (const float*)d_in[14];
    const float* gamma = (const float*)d_in[15];
    float* out = (float*)d_out;

    prep_kernel<<<BHW, C_>>>(x, Wq, bq, gq, betaq, mq, vq,
                             Wk, bk, gk, betak, mk, vk, Wv, bv);
    exp_kernel<<<dim3(NMT, NMT, B_), 256>>>();
    rsum_kernel<<<BHW / 256, 256>>>();
    scalev_kernel<<<(unsigned)(((size_t)B_ * C_ * HW_) / 256), 256>>>(gamma);
    gemm_kernel<<<dim3(HW_ / 64, B_), 256>>>(x, out);
}